// round 3
// baseline (speedup 1.0000x reference)
#include <cuda_runtime.h>
#include <stdint.h>

#define NLEV      5
#define NCLS      80
#define M_TOTAL   4900
#define CAND_CAP  4096
#define NBINS     2048
#define IMG_F     1280.0f
#define CONF_T    0.05f
#define NMS_T     0.6f

__constant__ int d_LN[NLEV] = {230400, 57600, 14400, 3600, 900};

// -------- scratch (device globals; no allocation allowed) --------
__device__ unsigned           g_hist[NLEV][NBINS];
__device__ int                g_tbin[NLEV];
__device__ int                g_ccount[NLEV];
__device__ unsigned long long g_ckeys[NLEV][CAND_CAP];

__device__ float  g_score[M_TOTAL];
__device__ int    g_label[M_TOTAL];
__device__ float4 g_box[M_TOTAL];

__device__ float  g_sscore[M_TOTAL];
__device__ int    g_slabel[M_TOTAL];
__device__ float4 g_sbox[M_TOTAL];
__device__ int    g_svalid[M_TOTAL];
__device__ int    g_keep[M_TOTAL];

struct PtrSet { const float4* p[NLEV]; };

// monotone float -> uint map (order preserving)
__device__ __forceinline__ unsigned fmap(float x) {
    unsigned u = __float_as_uint(x);
    return (u & 0x80000000u) ? ~u : (u | 0x80000000u);
}

// ---------------- init scratch ----------------
__global__ void k_init() {
    int t = blockIdx.x * blockDim.x + threadIdx.x;
    if (t < NLEV * NBINS) ((unsigned*)g_hist)[t] = 0;
    if (t < NLEV) g_ccount[t] = 0;
    if (t < M_TOTAL) g_keep[t] = 0;
}

// ---------------- pass 1: histogram of positive logits ----------------
__global__ void k_hist(PtrSet cls) {
    int lev = blockIdx.y;
    int n4 = d_LN[lev] * NCLS / 4;
    __shared__ unsigned sh[NBINS];
    for (int i = threadIdx.x; i < NBINS; i += blockDim.x) sh[i] = 0;
    __syncthreads();
    const float4* p = cls.p[lev];
    for (int i = blockIdx.x * blockDim.x + threadIdx.x; i < n4;
         i += gridDim.x * blockDim.x) {
        float4 v = p[i];
        if (v.x > 0.f) atomicAdd(&sh[(fmap(v.x) >> 20) - 2048u], 1u);
        if (v.y > 0.f) atomicAdd(&sh[(fmap(v.y) >> 20) - 2048u], 1u);
        if (v.z > 0.f) atomicAdd(&sh[(fmap(v.z) >> 20) - 2048u], 1u);
        if (v.w > 0.f) atomicAdd(&sh[(fmap(v.w) >> 20) - 2048u], 1u);
    }
    __syncthreads();
    for (int i = threadIdx.x; i < NBINS; i += blockDim.x)
        if (sh[i]) atomicAdd(&g_hist[lev][i], sh[i]);
}

// ---------------- select per-level threshold bin ----------------
__global__ void k_select() {
    int lev = threadIdx.x;
    if (lev >= NLEV) return;
    int k = (lev == 4) ? 900 : 1000;
    unsigned cum = 0;
    int b = 0;
    for (int i = NBINS - 1; i >= 0; i--) {
        cum += g_hist[lev][i];
        if (cum >= (unsigned)k) { b = i; break; }
    }
    g_tbin[lev] = b;
}

// ---------------- pass 2: compact candidates ----------------
__global__ void k_compact(PtrSet cls) {
    int lev = blockIdx.y;
    int n4 = d_LN[lev] * NCLS / 4;
    unsigned ut = ((unsigned)(g_tbin[lev] + 2048)) << 20;
    const float4* p = cls.p[lev];
    for (int i = blockIdx.x * blockDim.x + threadIdx.x; i < n4;
         i += gridDim.x * blockDim.x) {
        float4 v = p[i];
        unsigned base = (unsigned)i * 4u;
        float vals[4] = {v.x, v.y, v.z, v.w};
        #pragma unroll
        for (int c = 0; c < 4; c++) {
            unsigned u = fmap(vals[c]);
            if (u >= ut) {
                int pos = atomicAdd(&g_ccount[lev], 1);
                if (pos < CAND_CAP)
                    g_ckeys[lev][pos] =
                        ((unsigned long long)u << 32) |
                        (unsigned long long)(0xFFFFFFFFu - (base + c));
            }
        }
    }
}

// ---------------- bitonic sort (descending) in shared memory ----------------
__device__ __forceinline__ void bitonic_desc(unsigned long long* sk, int N) {
    for (int size = 2; size <= N; size <<= 1) {
        for (int stride = size >> 1; stride > 0; stride >>= 1) {
            __syncthreads();
            for (int t = threadIdx.x; t < (N >> 1); t += blockDim.x) {
                int i = ((t & ~(stride - 1)) << 1) | (t & (stride - 1));
                int j = i | stride;
                unsigned long long a = sk[i], b = sk[j];
                bool desc = ((i & size) == 0);
                if ((a < b) == desc) { sk[i] = b; sk[j] = a; }
            }
        }
    }
    __syncthreads();
}

// ---------------- per-level: sort candidates, emit exact top-k ----------------
__global__ void k_lsort(PtrSet boxes) {
    __shared__ unsigned long long sk[CAND_CAP];
    int lev = blockIdx.x;
    int cc = min(g_ccount[lev], CAND_CAP);
    for (int i = threadIdx.x; i < CAND_CAP; i += blockDim.x)
        sk[i] = (i < cc) ? g_ckeys[lev][i] : 0ULL;
    __syncthreads();
    bitonic_desc(sk, CAND_CAP);
    int k = (lev == 4) ? 900 : 1000;
    int off = lev * 1000;
    const float4* bx = boxes.p[lev];
    for (int r = threadIdx.x; r < k; r += blockDim.x) {
        unsigned long long key = sk[r];
        unsigned u = (unsigned)(key >> 32);
        float logit = __uint_as_float(u & 0x7FFFFFFFu);
        float score = 1.0f / (1.0f + expf(-logit));
        unsigned flat = 0xFFFFFFFFu - (unsigned)(key & 0xFFFFFFFFull);
        int label = (int)(flat % NCLS);
        int anchor = (int)(flat / NCLS);
        g_score[off + r] = score;
        g_label[off + r] = label;
        g_box[off + r] = bx[anchor];
    }
}

// ---------------- global sort of 4900 by masked score (stable tie-break) ----
__global__ void k_gsort() {
    extern __shared__ unsigned long long sk[];
    const int N = 8192;
    for (int i = threadIdx.x; i < N; i += blockDim.x) {
        unsigned long long key = 0ULL;
        if (i < M_TOTAL) {
            float sc = g_score[i];
            float sval = (sc > CONF_T) ? sc : 0.0f;
            key = ((unsigned long long)fmap(sval) << 32) |
                  (unsigned long long)(0xFFFFFFFFu - (unsigned)i);
        }
        sk[i] = key;
    }
    __syncthreads();
    bitonic_desc(sk, N);
    for (int r = threadIdx.x; r < M_TOTAL; r += blockDim.x) {
        unsigned long long key = sk[r];
        int idx = (int)(0xFFFFFFFFu - (unsigned)(key & 0xFFFFFFFFull));
        float sval = __uint_as_float(((unsigned)(key >> 32)) & 0x7FFFFFFFu);
        g_sscore[r] = sval;
        g_slabel[r] = g_label[idx];
        g_sbox[r] = g_box[idx];
        g_svalid[r] = (sval > CONF_T) ? 1 : 0;
    }
}

// ---------------- per-class greedy NMS (cross-class IoU is exactly 0) ------
__global__ void k_nms() {
    int c = blockIdx.x;
    int lane = threadIdx.x;  // 32 threads
    __shared__ int    s_pos[512];
    __shared__ float4 s_b[512];
    __shared__ float  s_area[512];
    __shared__ int    s_alive[512];

    int m = 0;
    for (int base = 0; base < M_TOTAL; base += 32) {
        int t = base + lane;
        bool hit = (t < M_TOTAL) && (g_slabel[t] == c) && (g_svalid[t] != 0);
        unsigned bal = __ballot_sync(0xFFFFFFFFu, hit);
        if (hit) {
            int p = m + __popc(bal & ((1u << lane) - 1u));
            if (p < 512) {
                float4 b = g_sbox[t];
                s_pos[p] = t;
                s_b[p] = b;
                s_area[p] = fmaxf(b.z - b.x, 0.f) * fmaxf(b.w - b.y, 0.f);
                s_alive[p] = 1;
            }
        }
        m += __popc(bal);
    }
    m = min(m, 512);
    __syncwarp();

    for (int i = 0; i < m; i++) {
        bool live = (s_alive[i] != 0);  // uniform across warp
        if (live) {
            float4 bi = s_b[i];
            float ai = s_area[i];
            for (int j = i + 1 + lane; j < m; j += 32) {
                if (s_alive[j]) {
                    float4 bj = s_b[j];
                    float lx = fmaxf(bi.x, bj.x), ly = fmaxf(bi.y, bj.y);
                    float rx = fminf(bi.z, bj.z), ry = fminf(bi.w, bj.w);
                    float iw = fmaxf(rx - lx, 0.f), ih = fmaxf(ry - ly, 0.f);
                    float inter = iw * ih;
                    float iou = inter / (ai + s_area[j] - inter + 1e-9f);
                    if (iou > NMS_T) s_alive[j] = 0;
                }
            }
        }
        __syncwarp();
    }
    for (int j = lane; j < m; j += 32) g_keep[s_pos[j]] = s_alive[j];
}

// ---------------- final output write ----------------
__global__ void k_write(float* __restrict__ out) {
    int t = blockIdx.x * blockDim.x + threadIdx.x;
    if (t >= M_TOTAL) return;
    float kf = g_keep[t] ? 1.0f : 0.0f;
    float4 b = g_sbox[t];
    const float inv = 1.0f / IMG_F;
    out[t * 4 + 0] = fminf(fmaxf(b.x * inv, 0.f), 1.f) * kf;
    out[t * 4 + 1] = fminf(fmaxf(b.y * inv, 0.f), 1.f) * kf;
    out[t * 4 + 2] = fminf(fmaxf(b.z * inv, 0.f), 1.f) * kf;
    out[t * 4 + 3] = fminf(fmaxf(b.w * inv, 0.f), 1.f) * kf;
    out[4 * M_TOTAL + t] = g_sscore[t] * kf;
    out[5 * M_TOTAL + t] = (float)g_slabel[t];
    out[6 * M_TOTAL + t] = kf;
}

extern "C" void kernel_launch(void* const* d_in, const int* in_sizes, int n_in,
                              void* d_out, int out_size) {
    (void)in_sizes; (void)n_in; (void)out_size;
    // metadata order is INTERLEAVED: cls0, box0, cls1, box1, ...
    PtrSet cls, box;
    for (int i = 0; i < NLEV; i++) {
        cls.p[i] = (const float4*)d_in[2 * i];
        box.p[i] = (const float4*)d_in[2 * i + 1];
    }
    float* out = (float*)d_out;

    k_init<<<48, 256>>>();
    k_hist<<<dim3(1024, NLEV), 256>>>(cls);
    k_select<<<1, 32>>>();
    k_compact<<<dim3(1024, NLEV), 256>>>(cls);
    k_lsort<<<NLEV, 1024>>>(box);
    cudaFuncSetAttribute(k_gsort, cudaFuncAttributeMaxDynamicSharedMemorySize,
                         8192 * sizeof(unsigned long long));
    k_gsort<<<1, 1024, 8192 * sizeof(unsigned long long)>>>();
    k_nms<<<NCLS, 32>>>();
    k_write<<<(M_TOTAL + 255) / 256, 256>>>(out);
}

// round 4
// speedup vs baseline: 1.2917x; 1.2917x over previous
#include <cuda_runtime.h>
#include <stdint.h>

#define NLEV      5
#define NCLS      80
#define M_TOTAL   4900
#define CAND_CAP  4096
#define NBINS     2048
#define IMG_F     1280.0f
#define CONF_T    0.05f
#define NMS_T     0.6f
#define STG_CAP   2048

__constant__ int d_LN[NLEV]   = {230400, 57600, 14400, 3600, 900};
__constant__ int c_coff[NLEV] = {0, 786432, 983040, 1048576, 1064960};
__constant__ int c_ccap[NLEV] = {786432, 196608, 65536, 16384, 8192};
#define CAND_TOTAL 1073152

// -------- scratch (device globals; no allocation allowed) --------
__device__ unsigned long long g_cand[CAND_TOTAL];   // stage-1 positives
__device__ int                g_ccount0[NLEV];      // stage-1 counts
__device__ unsigned           g_hist[NLEV][NBINS];
__device__ int                g_tbin[NLEV];
__device__ int                g_ccount[NLEV];       // stage-2 counts
__device__ unsigned long long g_ckeys[NLEV][CAND_CAP];

__device__ float  g_score[M_TOTAL];
__device__ int    g_label[M_TOTAL];
__device__ float4 g_box[M_TOTAL];

__device__ float  g_sscore[M_TOTAL];
__device__ int    g_slabel[M_TOTAL];
__device__ float4 g_sbox[M_TOTAL];
__device__ int    g_svalid[M_TOTAL];
__device__ int    g_keep[M_TOTAL];

struct PtrSet { const float4* p[NLEV]; };

// monotone float -> uint map for positive floats
__device__ __forceinline__ unsigned fmap_pos(float x) {
    return __float_as_uint(x) | 0x80000000u;
}
__device__ __forceinline__ unsigned fmap(float x) {
    unsigned u = __float_as_uint(x);
    return (u & 0x80000000u) ? ~u : (u | 0x80000000u);
}

// ---------------- init scratch ----------------
__global__ void k_init() {
    int t = blockIdx.x * blockDim.x + threadIdx.x;
    if (t < NLEV * NBINS) ((unsigned*)g_hist)[t] = 0;
    if (t < NLEV) { g_ccount0[t] = 0; g_ccount[t] = 0; }
    if (t < M_TOTAL) g_keep[t] = 0;
}

// ---------------- pass 1: stream 98MB once, compact positive logits --------
__global__ void k_filter(PtrSet cls) {
    int lev = blockIdx.y;
    int n4 = d_LN[lev] * (NCLS / 4);
    __shared__ unsigned long long stg[STG_CAP];
    __shared__ int s_cnt;
    __shared__ int s_base;
    if (threadIdx.x == 0) s_cnt = 0;
    __syncthreads();

    const float4* __restrict__ p = cls.p[lev];
    unsigned long long* cand = g_cand + c_coff[lev];
    int cap = c_ccap[lev];
    int stride = gridDim.x * blockDim.x;

    for (int i = blockIdx.x * blockDim.x + threadIdx.x; i < n4; i += stride) {
        float4 v = p[i];
        unsigned base = (unsigned)i * 4u;
        float vals[4] = {v.x, v.y, v.z, v.w};
        #pragma unroll
        for (int c = 0; c < 4; c++) {
            if (vals[c] > 0.f) {
                unsigned long long key =
                    ((unsigned long long)fmap_pos(vals[c]) << 32) |
                    (unsigned long long)(0xFFFFFFFFu - (base + c));
                int pos = atomicAdd(&s_cnt, 1);
                if (pos < STG_CAP) stg[pos] = key;
                else {  // staging overflow fallback (deterministically rare)
                    int gp = atomicAdd(&g_ccount0[lev], 1);
                    if (gp < cap) cand[gp] = key;
                }
            }
        }
    }
    __syncthreads();
    int cnt = min(s_cnt, STG_CAP);
    if (threadIdx.x == 0) s_base = atomicAdd(&g_ccount0[lev], cnt);
    __syncthreads();
    for (int i = threadIdx.x; i < cnt; i += blockDim.x) {
        int gp = s_base + i;
        if (gp < cap) cand[gp] = stg[i];
    }
}

// ---------------- histogram over candidates (~4.5MB) ----------------
__global__ void k_hist2() {
    int lev = blockIdx.y;
    int cc = min(g_ccount0[lev], c_ccap[lev]);
    __shared__ unsigned sh[NBINS];
    for (int i = threadIdx.x; i < NBINS; i += blockDim.x) sh[i] = 0;
    __syncthreads();
    const unsigned long long* cand = g_cand + c_coff[lev];
    for (int i = blockIdx.x * blockDim.x + threadIdx.x; i < cc;
         i += gridDim.x * blockDim.x) {
        unsigned u = (unsigned)(cand[i] >> 32);
        atomicAdd(&sh[(u >> 20) - 2048u], 1u);
    }
    __syncthreads();
    for (int i = threadIdx.x; i < NBINS; i += blockDim.x)
        if (sh[i]) atomicAdd(&g_hist[lev][i], sh[i]);
}

// ---------------- parallel threshold-bin selection (suffix scan) ----------
__global__ void k_selpar() {
    int lev = blockIdx.x;
    __shared__ unsigned s[NBINS];
    int i0 = threadIdx.x, i1 = threadIdx.x + 1024;
    s[i0] = g_hist[lev][i0];
    s[i1] = g_hist[lev][i1];
    __syncthreads();
    for (int str = 1; str < NBINS; str <<= 1) {
        unsigned v0 = s[i0] + ((i0 + str < NBINS) ? s[i0 + str] : 0u);
        unsigned v1 = s[i1] + ((i1 + str < NBINS) ? s[i1 + str] : 0u);
        __syncthreads();
        s[i0] = v0; s[i1] = v1;
        __syncthreads();
    }
    unsigned k = (lev == 4) ? 900u : 1000u;
    if (threadIdx.x == 0 && s[0] < k) g_tbin[lev] = 0;  // fallback (never hit)
    #pragma unroll
    for (int rep = 0; rep < 2; rep++) {
        int idx = (rep == 0) ? i0 : i1;
        if (s[idx] >= k && (idx == NBINS - 1 || s[idx + 1] < k))
            g_tbin[lev] = idx;
    }
}

// ---------------- compact candidates above threshold (<=4096/level) -------
__global__ void k_compact2() {
    int lev = blockIdx.y;
    int cc = min(g_ccount0[lev], c_ccap[lev]);
    unsigned ut = ((unsigned)(g_tbin[lev] + 2048)) << 20;
    const unsigned long long* cand = g_cand + c_coff[lev];
    for (int i = blockIdx.x * blockDim.x + threadIdx.x; i < cc;
         i += gridDim.x * blockDim.x) {
        unsigned long long key = cand[i];
        if ((unsigned)(key >> 32) >= ut) {
            int pos = atomicAdd(&g_ccount[lev], 1);
            if (pos < CAND_CAP) g_ckeys[lev][pos] = key;
        }
    }
}

// ---------------- bitonic sort (descending) in shared memory --------------
__device__ __forceinline__ void bitonic_desc(unsigned long long* sk, int N) {
    for (int size = 2; size <= N; size <<= 1) {
        for (int stride = size >> 1; stride > 0; stride >>= 1) {
            __syncthreads();
            for (int t = threadIdx.x; t < (N >> 1); t += blockDim.x) {
                int i = ((t & ~(stride - 1)) << 1) | (t & (stride - 1));
                int j = i | stride;
                unsigned long long a = sk[i], b = sk[j];
                bool desc = ((i & size) == 0);
                if ((a < b) == desc) { sk[i] = b; sk[j] = a; }
            }
        }
    }
    __syncthreads();
}

// ---------------- per-level: sort candidates, emit exact top-k ------------
__global__ void k_lsort(PtrSet boxes) {
    __shared__ unsigned long long sk[CAND_CAP];
    int lev = blockIdx.x;
    int cc = min(g_ccount[lev], CAND_CAP);
    int N = 1024;
    while (N < cc) N <<= 1;
    for (int i = threadIdx.x; i < N; i += blockDim.x)
        sk[i] = (i < cc) ? g_ckeys[lev][i] : 0ULL;
    __syncthreads();
    bitonic_desc(sk, N);
    int k = (lev == 4) ? 900 : 1000;
    int off = lev * 1000;
    const float4* __restrict__ bx = boxes.p[lev];
    for (int r = threadIdx.x; r < k; r += blockDim.x) {
        unsigned long long key = sk[r];
        unsigned u = (unsigned)(key >> 32);
        float logit = __uint_as_float(u & 0x7FFFFFFFu);
        float score = 1.0f / (1.0f + expf(-logit));
        unsigned flat = 0xFFFFFFFFu - (unsigned)(key & 0xFFFFFFFFull);
        int label = (int)(flat % NCLS);
        int anchor = (int)(flat / NCLS);
        g_score[off + r] = score;
        g_label[off + r] = label;
        g_box[off + r] = bx[anchor];
    }
}

// ---------------- global sort of 4900 by masked score ---------------------
__global__ void k_gsort() {
    extern __shared__ unsigned long long sk[];
    const int N = 8192;
    for (int i = threadIdx.x; i < N; i += blockDim.x) {
        unsigned long long key = 0ULL;
        if (i < M_TOTAL) {
            float sc = g_score[i];
            float sval = (sc > CONF_T) ? sc : 0.0f;
            key = ((unsigned long long)fmap(sval) << 32) |
                  (unsigned long long)(0xFFFFFFFFu - (unsigned)i);
        }
        sk[i] = key;
    }
    __syncthreads();
    bitonic_desc(sk, N);
    for (int r = threadIdx.x; r < M_TOTAL; r += blockDim.x) {
        unsigned long long key = sk[r];
        int idx = (int)(0xFFFFFFFFu - (unsigned)(key & 0xFFFFFFFFull));
        float sval = __uint_as_float(((unsigned)(key >> 32)) & 0x7FFFFFFFu);
        g_sscore[r] = sval;
        g_slabel[r] = g_label[idx];
        g_sbox[r] = g_box[idx];
        g_svalid[r] = (sval > CONF_T) ? 1 : 0;
    }
}

// ---------------- per-class greedy NMS (cross-class IoU exactly 0) --------
__global__ void k_nms() {
    int c = blockIdx.x;
    int lane = threadIdx.x;  // 32 threads
    __shared__ int    s_pos[512];
    __shared__ float4 s_b[512];
    __shared__ float  s_area[512];
    __shared__ int    s_alive[512];

    int m = 0;
    for (int base = 0; base < M_TOTAL; base += 32) {
        int t = base + lane;
        bool hit = (t < M_TOTAL) && (g_slabel[t] == c) && (g_svalid[t] != 0);
        unsigned bal = __ballot_sync(0xFFFFFFFFu, hit);
        if (hit) {
            int p = m + __popc(bal & ((1u << lane) - 1u));
            if (p < 512) {
                float4 b = g_sbox[t];
                s_pos[p] = t;
                s_b[p] = b;
                s_area[p] = fmaxf(b.z - b.x, 0.f) * fmaxf(b.w - b.y, 0.f);
                s_alive[p] = 1;
            }
        }
        m += __popc(bal);
    }
    m = min(m, 512);
    __syncwarp();

    for (int i = 0; i < m; i++) {
        bool live = (s_alive[i] != 0);
        if (live) {
            float4 bi = s_b[i];
            float ai = s_area[i];
            for (int j = i + 1 + lane; j < m; j += 32) {
                if (s_alive[j]) {
                    float4 bj = s_b[j];
                    float lx = fmaxf(bi.x, bj.x), ly = fmaxf(bi.y, bj.y);
                    float rx = fminf(bi.z, bj.z), ry = fminf(bi.w, bj.w);
                    float iw = fmaxf(rx - lx, 0.f), ih = fmaxf(ry - ly, 0.f);
                    float inter = iw * ih;
                    float iou = inter / (ai + s_area[j] - inter + 1e-9f);
                    if (iou > NMS_T) s_alive[j] = 0;
                }
            }
        }
        __syncwarp();
    }
    for (int j = lane; j < m; j += 32) g_keep[s_pos[j]] = s_alive[j];
}

// ---------------- final output write ----------------
__global__ void k_write(float* __restrict__ out) {
    int t = blockIdx.x * blockDim.x + threadIdx.x;
    if (t >= M_TOTAL) return;
    float kf = g_keep[t] ? 1.0f : 0.0f;
    float4 b = g_sbox[t];
    const float inv = 1.0f / IMG_F;
    out[t * 4 + 0] = fminf(fmaxf(b.x * inv, 0.f), 1.f) * kf;
    out[t * 4 + 1] = fminf(fmaxf(b.y * inv, 0.f), 1.f) * kf;
    out[t * 4 + 2] = fminf(fmaxf(b.z * inv, 0.f), 1.f) * kf;
    out[t * 4 + 3] = fminf(fmaxf(b.w * inv, 0.f), 1.f) * kf;
    out[4 * M_TOTAL + t] = g_sscore[t] * kf;
    out[5 * M_TOTAL + t] = (float)g_slabel[t];
    out[6 * M_TOTAL + t] = kf;
}

extern "C" void kernel_launch(void* const* d_in, const int* in_sizes, int n_in,
                              void* d_out, int out_size) {
    (void)in_sizes; (void)n_in; (void)out_size;
    // metadata order is INTERLEAVED: cls0, box0, cls1, box1, ...
    PtrSet cls, box;
    for (int i = 0; i < NLEV; i++) {
        cls.p[i] = (const float4*)d_in[2 * i];
        box.p[i] = (const float4*)d_in[2 * i + 1];
    }
    float* out = (float*)d_out;

    k_init<<<48, 256>>>();
    k_filter<<<dim3(1024, NLEV), 256>>>(cls);
    k_hist2<<<dim3(64, NLEV), 256>>>();
    k_selpar<<<NLEV, 1024>>>();
    k_compact2<<<dim3(64, NLEV), 256>>>();
    k_lsort<<<NLEV, 1024>>>(box);
    cudaFuncSetAttribute(k_gsort, cudaFuncAttributeMaxDynamicSharedMemorySize,
                         8192 * sizeof(unsigned long long));
    k_gsort<<<1, 1024, 8192 * sizeof(unsigned long long)>>>();
    k_nms<<<NCLS, 32>>>();
    k_write<<<(M_TOTAL + 255) / 256, 256>>>(out);
}

// round 5
// speedup vs baseline: 1.3233x; 1.0245x over previous
#include <cuda_runtime.h>
#include <stdint.h>

#define NLEV      5
#define NCLS      80
#define M_TOTAL   4900
#define CAND_CAP  4096
#define NBINS     2048
#define IMG_F     1280.0f
#define CONF_T    0.05f
#define NMS_T     0.6f
#define STG_CAP   2048

__constant__ int d_LN[NLEV]   = {230400, 57600, 14400, 3600, 900};
__constant__ int c_coff[NLEV] = {0, 786432, 983040, 1048576, 1064960};
__constant__ int c_ccap[NLEV] = {786432, 196608, 65536, 16384, 8192};
#define CAND_TOTAL 1073152

// block apportionment for k_filter (proportional to level size)
__constant__ int c_b0[NLEV] = {0, 960, 1200, 1260, 1275};
__constant__ int c_nb[NLEV] = {960, 240, 60, 15, 4};
#define FILTER_BLOCKS 1279

// -------- scratch (device globals; no allocation allowed) --------
__device__ unsigned long long g_cand[CAND_TOTAL];
__device__ int                g_ccount0[NLEV];
__device__ unsigned           g_hist[NLEV][NBINS];
__device__ int                g_ccount[NLEV];
__device__ unsigned long long g_ckeys[NLEV][CAND_CAP];

__device__ float  g_score[M_TOTAL];
__device__ int    g_label[M_TOTAL];
__device__ float4 g_box[M_TOTAL];

struct PtrSet { const float4* p[NLEV]; };

__device__ __forceinline__ unsigned fmap_pos(float x) {
    return __float_as_uint(x) | 0x80000000u;
}
__device__ __forceinline__ unsigned fmap(float x) {
    unsigned u = __float_as_uint(x);
    return (u & 0x80000000u) ? ~u : (u | 0x80000000u);
}

// ---------------- init scratch ----------------
__global__ void k_init() {
    int t = blockIdx.x * blockDim.x + threadIdx.x;
    if (t < NLEV * NBINS) ((unsigned*)g_hist)[t] = 0;
    if (t < NLEV) { g_ccount0[t] = 0; g_ccount[t] = 0; }
}

// ------- pass 1: stream 98MB once; compact positives + histogram ----------
__global__ void k_filter(PtrSet cls) {
    int b = blockIdx.x;
    int lev = (b < 960) ? 0 : (b < 1200) ? 1 : (b < 1260) ? 2 : (b < 1275) ? 3 : 4;
    int brel = b - c_b0[lev];
    int nb   = c_nb[lev];
    int n4 = d_LN[lev] * (NCLS / 4);

    __shared__ unsigned long long stg[STG_CAP];
    __shared__ unsigned shist[NBINS];
    __shared__ int s_cnt, s_base;
    for (int i = threadIdx.x; i < NBINS; i += blockDim.x) shist[i] = 0;
    if (threadIdx.x == 0) s_cnt = 0;
    __syncthreads();

    const float4* __restrict__ p = cls.p[lev];
    unsigned long long* cand = g_cand + c_coff[lev];
    int cap = c_ccap[lev];
    int stride = nb * blockDim.x * 2;

    for (int i = (brel * blockDim.x + threadIdx.x) * 2; i < n4; i += stride) {
        float4 v0 = p[i];
        float4 v1 = (i + 1 < n4) ? p[i + 1] : make_float4(-1.f, -1.f, -1.f, -1.f);
        float vals[8] = {v0.x, v0.y, v0.z, v0.w, v1.x, v1.y, v1.z, v1.w};
        unsigned base = (unsigned)i * 4u;
        #pragma unroll
        for (int c = 0; c < 8; c++) {
            if (vals[c] > 0.f) {
                unsigned u = fmap_pos(vals[c]);
                atomicAdd(&shist[(u >> 20) - 2048u], 1u);
                unsigned long long key =
                    ((unsigned long long)u << 32) |
                    (unsigned long long)(0xFFFFFFFFu - (base + c));
                int pos = atomicAdd(&s_cnt, 1);
                if (pos < STG_CAP) stg[pos] = key;
                else {
                    int gp = atomicAdd(&g_ccount0[lev], 1);
                    if (gp < cap) cand[gp] = key;
                }
            }
        }
    }
    __syncthreads();
    int cnt = min(s_cnt, STG_CAP);
    if (threadIdx.x == 0) s_base = atomicAdd(&g_ccount0[lev], cnt);
    __syncthreads();
    for (int i = threadIdx.x; i < cnt; i += blockDim.x) {
        int gp = s_base + i;
        if (gp < cap) cand[gp] = stg[i];
    }
    for (int i = threadIdx.x; i < NBINS; i += blockDim.x)
        if (shist[i]) atomicAdd(&g_hist[lev][i], shist[i]);
}

// ------- threshold scan (per-block, redundant) + compact above it ---------
__global__ void k_compact2() {
    int lev = blockIdx.y;
    __shared__ unsigned s[NBINS];
    __shared__ int s_tbin;
    for (int i = threadIdx.x; i < NBINS; i += 256) s[i] = g_hist[lev][i];
    if (threadIdx.x == 0) s_tbin = 0;
    __syncthreads();
    // Hillis-Steele suffix sum over 2048 bins with 256 threads
    for (int str = 1; str < NBINS; str <<= 1) {
        unsigned v[NBINS / 256];
        #pragma unroll
        for (int r = 0; r < NBINS / 256; r++) {
            int idx = threadIdx.x + r * 256;
            v[r] = s[idx] + ((idx + str < NBINS) ? s[idx + str] : 0u);
        }
        __syncthreads();
        #pragma unroll
        for (int r = 0; r < NBINS / 256; r++) s[threadIdx.x + r * 256] = v[r];
        __syncthreads();
    }
    unsigned k = (lev == 4) ? 900u : 1000u;
    #pragma unroll
    for (int r = 0; r < NBINS / 256; r++) {
        int idx = threadIdx.x + r * 256;
        if (s[idx] >= k && (idx == NBINS - 1 || s[idx + 1] < k)) s_tbin = idx;
    }
    __syncthreads();
    unsigned ut = ((unsigned)(s_tbin + 2048)) << 20;

    int cc = min(g_ccount0[lev], c_ccap[lev]);
    const unsigned long long* cand = g_cand + c_coff[lev];
    for (int i = blockIdx.x * 256 + threadIdx.x; i < cc; i += gridDim.x * 256) {
        unsigned long long key = cand[i];
        if ((unsigned)(key >> 32) >= ut) {
            int pos = atomicAdd(&g_ccount[lev], 1);
            if (pos < CAND_CAP) g_ckeys[lev][pos] = key;
        }
    }
}

// ---------------- bitonic sort (descending) in shared memory --------------
__device__ __forceinline__ void bitonic_desc(unsigned long long* sk, int N) {
    for (int size = 2; size <= N; size <<= 1) {
        for (int stride = size >> 1; stride > 0; stride >>= 1) {
            __syncthreads();
            for (int t = threadIdx.x; t < (N >> 1); t += blockDim.x) {
                int i = ((t & ~(stride - 1)) << 1) | (t & (stride - 1));
                int j = i | stride;
                unsigned long long a = sk[i], b = sk[j];
                bool desc = ((i & size) == 0);
                if ((a < b) == desc) { sk[i] = b; sk[j] = a; }
            }
        }
    }
    __syncthreads();
}

// ------- per-level: sort candidates, emit exact sorted top-k --------------
__global__ void k_lsort(PtrSet boxes) {
    __shared__ unsigned long long sk[CAND_CAP];
    int lev = blockIdx.x;
    int cc = min(g_ccount[lev], CAND_CAP);
    int N = 1024;
    while (N < cc) N <<= 1;
    for (int i = threadIdx.x; i < N; i += blockDim.x)
        sk[i] = (i < cc) ? g_ckeys[lev][i] : 0ULL;
    __syncthreads();
    bitonic_desc(sk, N);
    int k = (lev == 4) ? 900 : 1000;
    int off = lev * 1000;
    const float4* __restrict__ bx = boxes.p[lev];
    for (int r = threadIdx.x; r < k; r += blockDim.x) {
        unsigned long long key = sk[r];
        unsigned u = (unsigned)(key >> 32);
        float logit = __uint_as_float(u & 0x7FFFFFFFu);
        float score = 1.0f / (1.0f + expf(-logit));
        unsigned flat = 0xFFFFFFFFu - (unsigned)(key & 0xFFFFFFFFull);
        int label = (int)(flat % NCLS);
        int anchor = (int)(flat / NCLS);
        g_score[off + r] = score;
        g_label[off + r] = label;
        g_box[off + r] = bx[anchor];
    }
}

// ------- fused tail: 5-way merge-rank + per-class NMS + output -------------
// shared layout (byte offsets)
#define T_KEYS   0            // 5000 * 8  = 40000
#define T_BOX    40000        // 4900 * 16 = 78400
#define T_SVAL   118400       // 4900 * 4  = 19600
#define T_CLCNT  138000       // 80 * 4    = 320
#define T_ORD    138320       // 4900 * 2  = 9800
#define T_CLL    148120       // 80*128*2  = 20480
#define T_LAB    168600       // 4900
#define T_ALIVE  173500       // 4900
#define T_SCLS   178400       // 4900
#define T_SMEM   183424

__global__ void k_tail(float* __restrict__ out) {
    extern __shared__ char sm[];
    unsigned long long* keys = (unsigned long long*)(sm + T_KEYS);
    float4* sbox  = (float4*)(sm + T_BOX);
    float*  sval  = (float*)(sm + T_SVAL);
    int*    clcnt = (int*)(sm + T_CLCNT);
    unsigned short* ord = (unsigned short*)(sm + T_ORD);
    unsigned short* cll = (unsigned short*)(sm + T_CLL);
    unsigned char*  slab   = (unsigned char*)(sm + T_LAB);
    unsigned char*  salive = (unsigned char*)(sm + T_ALIVE);
    unsigned char*  scls   = (unsigned char*)(sm + T_SCLS);

    int tid = threadIdx.x;
    // phase 1: load + build keys
    for (int i = tid; i < M_TOTAL; i += blockDim.x) {
        float sc = g_score[i];
        float sv = (sc > CONF_T) ? sc : 0.0f;
        sval[i] = sv;
        slab[i] = (unsigned char)g_label[i];
        sbox[i] = g_box[i];
        keys[i] = ((unsigned long long)fmap(sv) << 32) |
                  (unsigned long long)(0xFFFFFFFFu - (unsigned)i);
    }
    for (int i = M_TOTAL + tid; i < 5000; i += blockDim.x) keys[i] = 0ULL;
    if (tid < NCLS) clcnt[tid] = 0;
    __syncthreads();

    // phase 2: merge-rank via 4 binary searches (per-level arrays descending)
    for (int i = tid; i < M_TOTAL; i += blockDim.x) {
        unsigned long long myk = keys[i];
        int myLev = i / 1000;            // 4000..4899 -> 4
        int rank = i - myLev * 1000;
        #pragma unroll
        for (int L = 0; L < NLEV; L++) {
            if (L == myLev) continue;
            int base = L * 1000;
            int lo = 0, hi = 1000;
            while (lo < hi) {
                int mid = (lo + hi) >> 1;
                if (keys[base + mid] > myk) lo = mid + 1; else hi = mid;
            }
            rank += lo;
        }
        ord[rank] = (unsigned short)i;
    }
    __syncthreads();

    // phase 3: per-sorted-position class + alive; scatter to class lists
    for (int t = tid; t < M_TOTAL; t += blockDim.x) {
        int i = ord[t];
        unsigned char c = slab[i];
        scls[t] = c;
        salive[t] = (sval[i] > CONF_T) ? 1 : 0;
        int p = atomicAdd(&clcnt[c], 1);
        if (p < 128) cll[c * 128 + p] = (unsigned short)t;
    }
    __syncthreads();

    // phase 4: per-warp per-class: sort list ascending (by t) then greedy NMS
    int wid = tid >> 5, lane = tid & 31;
    for (int c = wid; c < NCLS; c += 32) {
        int m = min(clcnt[c], 128);
        unsigned short* L = cll + c * 128;
        for (int j = lane; j < 128; j += 32) if (j >= m) L[j] = 0xFFFF;
        __syncwarp();
        // 128-element bitonic ascending
        for (int size = 2; size <= 128; size <<= 1) {
            for (int str = size >> 1; str > 0; str >>= 1) {
                for (int q = lane; q < 64; q += 32) {
                    int a = ((q & ~(str - 1)) << 1) | (q & (str - 1));
                    int b = a | str;
                    unsigned short x = L[a], y = L[b];
                    bool up = ((a & size) == 0);
                    if ((x > y) == up) { L[a] = y; L[b] = x; }
                }
                __syncwarp();
            }
        }
        // greedy NMS over sorted class list
        for (int ii = 0; ii < m; ii++) {
            int ti = L[ii];
            if (salive[ti]) {
                float4 bi = sbox[ord[ti]];
                float ai = fmaxf(bi.z - bi.x, 0.f) * fmaxf(bi.w - bi.y, 0.f);
                for (int jj = ii + 1 + lane; jj < m; jj += 32) {
                    int tj = L[jj];
                    if (salive[tj]) {
                        float4 bj = sbox[ord[tj]];
                        float aj = fmaxf(bj.z - bj.x, 0.f) * fmaxf(bj.w - bj.y, 0.f);
                        float lx = fmaxf(bi.x, bj.x), ly = fmaxf(bi.y, bj.y);
                        float rx = fminf(bi.z, bj.z), ry = fminf(bi.w, bj.w);
                        float iw = fmaxf(rx - lx, 0.f), ih = fmaxf(ry - ly, 0.f);
                        float inter = iw * ih;
                        float iou = inter / (ai + aj - inter + 1e-9f);
                        if (iou > NMS_T) salive[tj] = 0;
                    }
                }
            }
            __syncwarp();
        }
    }
    __syncthreads();

    // phase 5: output
    const float inv = 1.0f / IMG_F;
    for (int t = tid; t < M_TOTAL; t += blockDim.x) {
        int i = ord[t];
        float kf = salive[t] ? 1.0f : 0.0f;
        float4 b = sbox[i];
        out[t * 4 + 0] = fminf(fmaxf(b.x * inv, 0.f), 1.f) * kf;
        out[t * 4 + 1] = fminf(fmaxf(b.y * inv, 0.f), 1.f) * kf;
        out[t * 4 + 2] = fminf(fmaxf(b.z * inv, 0.f), 1.f) * kf;
        out[t * 4 + 3] = fminf(fmaxf(b.w * inv, 0.f), 1.f) * kf;
        out[4 * M_TOTAL + t] = sval[i] * kf;
        out[5 * M_TOTAL + t] = (float)slab[i];
        out[6 * M_TOTAL + t] = kf;
    }
}

extern "C" void kernel_launch(void* const* d_in, const int* in_sizes, int n_in,
                              void* d_out, int out_size) {
    (void)in_sizes; (void)n_in; (void)out_size;
    // metadata order is INTERLEAVED: cls0, box0, cls1, box1, ...
    PtrSet cls, box;
    for (int i = 0; i < NLEV; i++) {
        cls.p[i] = (const float4*)d_in[2 * i];
        box.p[i] = (const float4*)d_in[2 * i + 1];
    }
    float* out = (float*)d_out;

    k_init<<<40, 256>>>();
    k_filter<<<FILTER_BLOCKS, 256>>>(cls);
    k_compact2<<<dim3(64, NLEV), 256>>>();
    k_lsort<<<NLEV, 1024>>>(box);
    cudaFuncSetAttribute(k_tail, cudaFuncAttributeMaxDynamicSharedMemorySize,
                         T_SMEM);
    k_tail<<<1, 1024, T_SMEM>>>(out);
}